// round 14
// baseline (speedup 1.0000x reference)
#include <cuda_runtime.h>
#include <cuda_fp16.h>
#include <math.h>
#include <cstdint>

#define L 64
#define R 4096
#define E 32
#define F 64
#define P 8

// ---- GEMM tiling: per block e fixed, 4 rt-tiles of M(r)=128, N(l)=64, K=64 ----
#define MT      128
#define TILES   4
#define GRIDY   (R / (MT * TILES))   // 8
#define SW      36            // smem row stride in b32 words; rows land on banks 4g+t

// epilogue half-buffer row stride (halfwords)
#define HS     136

// ---- RBF tiling ----
#define RTILE 256
#define NRT   (R / RTILE)    // 16

// RBF constants
#define DELTA      (10.0f / 31.0f)
#define INV_DELTA  (31.0f / 10.0f)
#define KC         3.8435917081166394f   // sqrt(log2 e)/|sigma|, sigma = -0.3125
#define DK         1.2398682929408514f   // DELTA * KC
#define DKSQ       1.5372733816041298f   // DK^2
#define C2R        0.1187050163f         // 2^(-2*DK^2)
#define WIN        2.0f

// scratch: atn[e][l][r] in fp16 (16.75 MB, L2-resident) + per-block partials
__device__ uint4 g_atn_u[E * L * R / 8];
__device__ float g_part[L * NRT * P];

__device__ __forceinline__ uint32_t s2u(const void* p) {
    uint32_t a;
    asm("{ .reg .u64 t; cvta.to.shared.u64 t, %1; cvt.u32.u64 %0, t; }"
        : "=r"(a) : "l"(p));
    return a;
}

// ---- bf16 helpers -------------------------------------------------------
__device__ __forceinline__ uint32_t pack_bf16(float hi_val, float lo_val) {
    uint32_t r;
    asm("cvt.rn.bf16x2.f32 %0, %1, %2;" : "=r"(r) : "f"(hi_val), "f"(lo_val));
    return r;
}
// split pair (x -> low half, y -> high half): h = bf16 his, l = bf16 residuals
__device__ __forceinline__ void split_pair(float x, float y,
                                           uint32_t& h, uint32_t& l) {
    h = pack_bf16(y, x);
    float fx = __uint_as_float(h << 16);
    float fy = __uint_as_float(h & 0xffff0000u);
    l = pack_bf16(y - fy, x - fx);
}
__device__ __forceinline__ void mma_bf16(float* d,
                                         uint32_t a0, uint32_t a1,
                                         uint32_t a2, uint32_t a3,
                                         uint32_t b0, uint32_t b1) {
    asm volatile(
        "mma.sync.aligned.m16n8k16.row.col.f32.bf16.bf16.f32 "
        "{%0,%1,%2,%3}, {%4,%5,%6,%7}, {%8,%9}, {%0,%1,%2,%3};"
        : "+f"(d[0]), "+f"(d[1]), "+f"(d[2]), "+f"(d[3])
        : "r"(a0), "r"(a1), "r"(a2), "r"(a3), "r"(b0), "r"(b1));
}
__device__ __forceinline__ void ldsm_x4(uint32_t* r, uint32_t addr) {
    asm volatile("ldmatrix.sync.aligned.m8n8.x4.shared.b16 {%0,%1,%2,%3}, [%4];"
        : "=r"(r[0]), "=r"(r[1]), "=r"(r[2]), "=r"(r[3]) : "r"(addr));
}

// ---------------------------------------------------------------------------
// Kernel A: 3xBF16 mma.sync m16n8k16, 4-tile software pipeline.
// grid (E, 8), 256 threads (8 warps as 4(r) x 2(l)); warp tile 32r x 32l.
// lig split once per block; next tile's rec LDGs issued before MMA.
// ---------------------------------------------------------------------------
#define S_LH 0
#define S_LL (64 * SW)
#define S_RH (2 * 64 * SW)
#define S_RL (2 * 64 * SW + 128 * SW)
#define S_EPI (2 * 64 * SW + 2 * 128 * SW)      // 13824 words
#define S_WORDS (S_EPI + (64 * HS) / 2)          // +4352 words -> 72704 B

__global__ __launch_bounds__(256)
void atn_mma(const float* __restrict__ lig, const float* __restrict__ rec) {
    extern __shared__ uint32_t sm[];
    const int e   = blockIdx.x;
    const int tb  = blockIdx.y << 2;   // first tile index
    const int tid = threadIdx.x;

    // ---- load + split lig tile [64 l][64 f] (once per block) ----
#pragma unroll
    for (int it = 0; it < 4; it++) {
        int idx = tid + (it << 8);
        int row = idx >> 4, f4 = idx & 15;
        float4 v = *(const float4*)(lig + ((row * E + e) << 6) + (f4 << 2));
        uint32_t h0, l0, h1, l1;
        split_pair(v.x, v.y, h0, l0);
        split_pair(v.z, v.w, h1, l1);
        int base = row * SW + (f4 << 1);
        *(uint2*)(sm + S_LH + base) = make_uint2(h0, h1);
        *(uint2*)(sm + S_LL + base) = make_uint2(l0, l1);
    }

    // ---- per-thread rec addressing (8 float4s of a 128x64 tile) ----
    int vrow[8], vf4[8];
#pragma unroll
    for (int it = 0; it < 8; it++) {
        int idx = tid + (it << 8);
        vrow[it] = idx >> 4;
        vf4[it]  = idx & 15;
    }

    // ---- preload rec tile 0 into registers ----
    float4 v[8];
    {
        const int rt0 = tb * MT;
#pragma unroll
        for (int it = 0; it < 8; it++)
            v[it] = *(const float4*)(rec + (((rt0 + vrow[it]) * E + e) << 6) + (vf4[it] << 2));
    }

    const int wid = tid >> 5;
    const int lid = tid & 31;
    const int g   = lid >> 2;
    const int t   = lid & 3;
    const int mb  = (wid & 3) << 5;  // warp r-base (0,32,64,96)
    const int nb  = (wid >> 2) << 5; // warp l-base (0,32)

    // ldmatrix lane-group addressing
    const int i8 = lid & 7;
    const int q  = lid >> 3;
    const uint32_t sb = s2u(sm);

    uint32_t a_h[2], a_l[2], b_h[2], b_l[2];
#pragma unroll
    for (int mt = 0; mt < 2; mt++) {
        int row = mb + (mt << 4) + ((q & 1) << 3) + i8;
        uint32_t off = (uint32_t)(row * SW + ((q >> 1) << 2)) << 2;
        a_h[mt] = sb + (S_RH << 2) + off;
        a_l[mt] = sb + (S_RL << 2) + off;
    }
#pragma unroll
    for (int jp = 0; jp < 2; jp++) {
        int row = nb + (jp << 4) + ((q >> 1) << 3) + i8;
        uint32_t off = (uint32_t)(row * SW + ((q & 1) << 2)) << 2;
        b_h[jp] = sb + (S_LH << 2) + off;
        b_l[jp] = sb + (S_LL << 2) + off;
    }

    __half* sm_h = reinterpret_cast<__half*>(sm + S_EPI);
    __half* ga   = reinterpret_cast<__half*>(g_atn_u);
    const int lrow = tid >> 2, qq = tid & 3;

#pragma unroll
    for (int tile = 0; tile < TILES; tile++) {
        const int rt = (tb + tile) * MT;

        // ---- split current rec regs -> bf16 smem ----
#pragma unroll
        for (int it = 0; it < 8; it++) {
            uint32_t h0, l0, h1, l1;
            split_pair(v[it].x, v[it].y, h0, l0);
            split_pair(v[it].z, v[it].w, h1, l1);
            int base = vrow[it] * SW + (vf4[it] << 1);
            *(uint2*)(sm + S_RH + base) = make_uint2(h0, h1);
            *(uint2*)(sm + S_RL + base) = make_uint2(l0, l1);
        }
        // ---- prefetch next tile's rec into regs (latency hides under MMA) ----
        if (tile < TILES - 1) {
            const int rtn = (tb + tile + 1) * MT;
#pragma unroll
            for (int it = 0; it < 8; it++)
                v[it] = *(const float4*)(rec + (((rtn + vrow[it]) * E + e) << 6) + (vf4[it] << 2));
        }
        __syncthreads();   // bar1: splits (and lig on tile 0) visible

        float d[2][4][4];
#pragma unroll
        for (int mt = 0; mt < 2; mt++)
#pragma unroll
            for (int j = 0; j < 4; j++)
#pragma unroll
                for (int c = 0; c < 4; c++) d[mt][j][c] = 0.0f;

#pragma unroll
        for (int ks = 0; ks < 4; ks++) {
            const uint32_t wb = (uint32_t)ks << 5;
            uint32_t AH[2][4], AL[2][4], BH[2][4], BL[2][4];
            ldsm_x4(AH[0], a_h[0] + wb);  ldsm_x4(AH[1], a_h[1] + wb);
            ldsm_x4(AL[0], a_l[0] + wb);  ldsm_x4(AL[1], a_l[1] + wb);
            ldsm_x4(BH[0], b_h[0] + wb);  ldsm_x4(BH[1], b_h[1] + wb);
            ldsm_x4(BL[0], b_l[0] + wb);  ldsm_x4(BL[1], b_l[1] + wb);

#pragma unroll
            for (int mt = 0; mt < 2; mt++)
#pragma unroll
                for (int jp = 0; jp < 2; jp++)
#pragma unroll
                    for (int jj = 0; jj < 2; jj++)
                        mma_bf16(d[mt][(jp << 1) + jj],
                                 AH[mt][0], AH[mt][1], AH[mt][2], AH[mt][3],
                                 BH[jp][jj << 1], BH[jp][(jj << 1) + 1]);
#pragma unroll
            for (int mt = 0; mt < 2; mt++)
#pragma unroll
                for (int jp = 0; jp < 2; jp++)
#pragma unroll
                    for (int jj = 0; jj < 2; jj++)
                        mma_bf16(d[mt][(jp << 1) + jj],
                                 AH[mt][0], AH[mt][1], AH[mt][2], AH[mt][3],
                                 BL[jp][jj << 1], BL[jp][(jj << 1) + 1]);
#pragma unroll
            for (int mt = 0; mt < 2; mt++)
#pragma unroll
                for (int jp = 0; jp < 2; jp++)
#pragma unroll
                    for (int jj = 0; jj < 2; jj++)
                        mma_bf16(d[mt][(jp << 1) + jj],
                                 AL[mt][0], AL[mt][1], AL[mt][2], AL[mt][3],
                                 BH[jp][jj << 1], BH[jp][(jj << 1) + 1]);
        }

        // ---- epilogue: transpose via dedicated smem, store fp16 coalesced ----
#pragma unroll
        for (int mt = 0; mt < 2; mt++)
#pragma unroll
            for (int j = 0; j < 4; j++) {
                const int l0 = nb + (j << 3) + (t << 1);
                const int r0 = mb + (mt << 4) + g;
                sm_h[ l0      * HS + r0    ] = __float2half(d[mt][j][0]);
                sm_h[(l0 + 1) * HS + r0    ] = __float2half(d[mt][j][1]);
                sm_h[ l0      * HS + r0 + 8] = __float2half(d[mt][j][2]);
                sm_h[(l0 + 1) * HS + r0 + 8] = __float2half(d[mt][j][3]);
            }
        __syncthreads();   // bar2: epi buffer filled; also all ldsm reads done

        {
            __half* dst = ga + ((long)((e << 6) + lrow)) * R + rt;
            const __half* src = sm_h + lrow * HS;
#pragma unroll
            for (int i = 0; i < 4; i++) {
                int off = (((i << 2) + qq) << 3);
                *(uint4*)(dst + off) = *(const uint4*)(src + off);
            }
        }
    }
}

// ---------------------------------------------------------------------------
// Kernel B: windowed RBF with multiplicative recurrence; fp16 stage-in.
// ---------------------------------------------------------------------------
__global__ __launch_bounds__(256) void rbf_energy(const float* __restrict__ ligc,
                                                  const float* __restrict__ recc) {
    const int l   = blockIdx.x;
    const int rt  = blockIdx.y * RTILE;
    const int tid = threadIdx.x;

    __shared__ float s_a[E][256];
    __shared__ float s_lc[P][3];
    __shared__ float s_red[8][P];

    if (tid < P * 3) {
        int p = tid / 3, cc = tid % 3;
        s_lc[p][cc] = ligc[p * (L * 3) + l * 3 + cc];
    }
    {
        const __half* ga = reinterpret_cast<const __half*>(g_atn_u);
#pragma unroll
        for (int it = 0; it < 16; it++) {
            int s = tid + (it << 8);
            int e = s >> 7, rr = (s & 127) << 1;
            __half2 v = *(const __half2*)(ga + ((long)(e * L + l)) * R + rt + rr);
            float2 f = __half22float2(v);
            s_a[e][rr]     = f.x;
            s_a[e][rr + 1] = f.y;
        }
    }
    __syncthreads();

    const int r = rt + tid;
    const float cx = recc[3 * r + 0];
    const float cy = recc[3 * r + 1];
    const float cz = recc[3 * r + 2];

    float acc[P];
#pragma unroll
    for (int p = 0; p < P; p++) {
        float dx = s_lc[p][0] - cx;
        float dy = s_lc[p][1] - cy;
        float dz = s_lc[p][2] - cz;
        // eps added per-coordinate before sum, as in reference: +3*1e-10
        float d2 = fmaf(dx, dx, fmaf(dy, dy, fmaf(dz, dz, 3.0e-10f)));
        float d;
        asm("sqrt.approx.ftz.f32 %0, %1;" : "=f"(d) : "f"(d2));

        int elo = (int)ceilf((d - WIN) * INV_DELTA);
        if (elo < 0) elo = 0;
        int ehi = (int)floorf((d + WIN) * INV_DELTA);
        if (ehi > E - 1) ehi = E - 1;

        float s = (d - (float)elo * DELTA) * KC;
        float f, u;
        {
            float t0 = -s * s;
            asm("ex2.approx.ftz.f32 %0, %1;" : "=f"(f) : "f"(t0));
            float t1 = fmaf(2.0f * DK, s, -DKSQ);
            asm("ex2.approx.ftz.f32 %0, %1;" : "=f"(u) : "f"(t1));
        }
        float ap = 0.0f;
        for (int e = elo; e <= ehi; e++) {
            ap = fmaf(s_a[e][tid], f, ap);
            f *= u;
            u *= C2R;
        }
        acc[p] = ap;
    }

#pragma unroll
    for (int p = 0; p < P; p++) {
        float v = acc[p];
#pragma unroll
        for (int off = 16; off; off >>= 1)
            v += __shfl_down_sync(0xffffffffu, v, off);
        if ((tid & 31) == 0) s_red[tid >> 5][p] = v;
    }
    __syncthreads();
    if (tid < P) {
        float v = 0.0f;
#pragma unroll
        for (int w = 0; w < 8; w++) v += s_red[w][tid];
        g_part[(l * NRT + blockIdx.y) * P + tid] = v;
    }
}

// ---------------------------------------------------------------------------
// Kernel C: reduce partials, apply weight/bias
// ---------------------------------------------------------------------------
__global__ __launch_bounds__(256) void finalize_k(const float* __restrict__ w,
                                                  const float* __restrict__ b,
                                                  float* __restrict__ out) {
    const int p    = threadIdx.x >> 5;
    const int lane = threadIdx.x & 31;
    float s = 0.0f;
    for (int k = lane; k < L * NRT; k += 32) s += g_part[k * P + p];
#pragma unroll
    for (int off = 16; off; off >>= 1)
        s += __shfl_down_sync(0xffffffffu, s, off);
    if (lane == 0) out[p] = fmaf(s, *w, *b);
}

// ---------------------------------------------------------------------------
extern "C" void kernel_launch(void* const* d_in, const int* in_sizes, int n_in,
                              void* d_out, int out_size) {
    const float* lig_feat   = (const float*)d_in[0];
    const float* rec_feat   = (const float*)d_in[1];
    const float* lig_coords = (const float*)d_in[2];
    const float* rec_coord  = (const float*)d_in[3];
    const float* weight     = (const float*)d_in[4];
    const float* bias       = (const float*)d_in[5];
    float* out = (float*)d_out;

    const int smem = S_WORDS * (int)sizeof(uint32_t);   // 72704 B
    cudaFuncSetAttribute(atn_mma, cudaFuncAttributeMaxDynamicSharedMemorySize, smem);

    atn_mma   <<<dim3(E, GRIDY), 256, smem>>>(lig_feat, rec_feat);
    rbf_energy<<<dim3(L, NRT), 256>>>(lig_coords, rec_coord);
    finalize_k<<<1, 256>>>(weight, bias, out);
}

// round 15
// speedup vs baseline: 1.0130x; 1.0130x over previous
#include <cuda_runtime.h>
#include <cuda_fp16.h>
#include <math.h>
#include <cstdint>

#define L 64
#define R 4096
#define E 32
#define F 64
#define P 8

// ---- GEMM tiling: per block e fixed, 4 rt-tiles of M(r)=128, N(l)=64, K=64 ----
#define MT      128
#define TILES   4
#define GRIDY   (R / (MT * TILES))   // 8
#define SW      36            // smem row stride in b32 words; rows land on banks 4g+t

// epilogue half-buffer row stride (halfwords)
#define HS     136

// ---- RBF tiling ----
#define RTILE2 512
#define NRT2   (R / RTILE2)   // 8

// RBF constants
#define DELTA      (10.0f / 31.0f)
#define INV_DELTA  (31.0f / 10.0f)
#define KC         3.8435917081166394f   // sqrt(log2 e)/|sigma|, sigma = -0.3125
#define DK         1.2398682929408514f   // DELTA * KC
#define DKSQ       1.5372733816041298f   // DK^2
#define C2R        0.1187050163f         // 2^(-2*DK^2)
#define WIN        2.0f
#define NWIN       13                     // fixed window trip count

// scratch: atn[e][l][r] in fp16 (16.75 MB, L2-resident) + per-block partials
__device__ uint4 g_atn_u[E * L * R / 8];
__device__ float g_part[L * NRT2 * P];
__device__ int   g_done = 0;

__device__ __forceinline__ uint32_t s2u(const void* p) {
    uint32_t a;
    asm("{ .reg .u64 t; cvta.to.shared.u64 t, %1; cvt.u32.u64 %0, t; }"
        : "=r"(a) : "l"(p));
    return a;
}

// ---- bf16 helpers -------------------------------------------------------
__device__ __forceinline__ uint32_t pack_bf16(float hi_val, float lo_val) {
    uint32_t r;
    asm("cvt.rn.bf16x2.f32 %0, %1, %2;" : "=r"(r) : "f"(hi_val), "f"(lo_val));
    return r;
}
__device__ __forceinline__ void split_pair(float x, float y,
                                           uint32_t& h, uint32_t& l) {
    h = pack_bf16(y, x);
    float fx = __uint_as_float(h << 16);
    float fy = __uint_as_float(h & 0xffff0000u);
    l = pack_bf16(y - fy, x - fx);
}
__device__ __forceinline__ void mma_bf16(float* d,
                                         uint32_t a0, uint32_t a1,
                                         uint32_t a2, uint32_t a3,
                                         uint32_t b0, uint32_t b1) {
    asm volatile(
        "mma.sync.aligned.m16n8k16.row.col.f32.bf16.bf16.f32 "
        "{%0,%1,%2,%3}, {%4,%5,%6,%7}, {%8,%9}, {%0,%1,%2,%3};"
        : "+f"(d[0]), "+f"(d[1]), "+f"(d[2]), "+f"(d[3])
        : "r"(a0), "r"(a1), "r"(a2), "r"(a3), "r"(b0), "r"(b1));
}
__device__ __forceinline__ void ldsm_x4(uint32_t* r, uint32_t addr) {
    asm volatile("ldmatrix.sync.aligned.m8n8.x4.shared.b16 {%0,%1,%2,%3}, [%4];"
        : "=r"(r[0]), "=r"(r[1]), "=r"(r[2]), "=r"(r[3]) : "r"(addr));
}

// ---------------------------------------------------------------------------
// Kernel A: 3xBF16 mma.sync m16n8k16, 4-tile software pipeline (R14, best A).
// ---------------------------------------------------------------------------
#define S_LH 0
#define S_LL (64 * SW)
#define S_RH (2 * 64 * SW)
#define S_RL (2 * 64 * SW + 128 * SW)
#define S_EPI (2 * 64 * SW + 2 * 128 * SW)
#define S_WORDS (S_EPI + (64 * HS) / 2)

__global__ __launch_bounds__(256)
void atn_mma(const float* __restrict__ lig, const float* __restrict__ rec) {
    extern __shared__ uint32_t sm[];
    const int e   = blockIdx.x;
    const int tb  = blockIdx.y << 2;
    const int tid = threadIdx.x;

#pragma unroll
    for (int it = 0; it < 4; it++) {
        int idx = tid + (it << 8);
        int row = idx >> 4, f4 = idx & 15;
        float4 v = *(const float4*)(lig + ((row * E + e) << 6) + (f4 << 2));
        uint32_t h0, l0, h1, l1;
        split_pair(v.x, v.y, h0, l0);
        split_pair(v.z, v.w, h1, l1);
        int base = row * SW + (f4 << 1);
        *(uint2*)(sm + S_LH + base) = make_uint2(h0, h1);
        *(uint2*)(sm + S_LL + base) = make_uint2(l0, l1);
    }

    int vrow[8], vf4[8];
#pragma unroll
    for (int it = 0; it < 8; it++) {
        int idx = tid + (it << 8);
        vrow[it] = idx >> 4;
        vf4[it]  = idx & 15;
    }

    float4 v[8];
    {
        const int rt0 = tb * MT;
#pragma unroll
        for (int it = 0; it < 8; it++)
            v[it] = *(const float4*)(rec + (((rt0 + vrow[it]) * E + e) << 6) + (vf4[it] << 2));
    }

    const int wid = tid >> 5;
    const int lid = tid & 31;
    const int g   = lid >> 2;
    const int t   = lid & 3;
    const int mb  = (wid & 3) << 5;
    const int nb  = (wid >> 2) << 5;

    const int i8 = lid & 7;
    const int q  = lid >> 3;
    const uint32_t sb = s2u(sm);

    uint32_t a_h[2], a_l[2], b_h[2], b_l[2];
#pragma unroll
    for (int mt = 0; mt < 2; mt++) {
        int row = mb + (mt << 4) + ((q & 1) << 3) + i8;
        uint32_t off = (uint32_t)(row * SW + ((q >> 1) << 2)) << 2;
        a_h[mt] = sb + (S_RH << 2) + off;
        a_l[mt] = sb + (S_RL << 2) + off;
    }
#pragma unroll
    for (int jp = 0; jp < 2; jp++) {
        int row = nb + (jp << 4) + ((q >> 1) << 3) + i8;
        uint32_t off = (uint32_t)(row * SW + ((q & 1) << 2)) << 2;
        b_h[jp] = sb + (S_LH << 2) + off;
        b_l[jp] = sb + (S_LL << 2) + off;
    }

    __half* sm_h = reinterpret_cast<__half*>(sm + S_EPI);
    __half* ga   = reinterpret_cast<__half*>(g_atn_u);
    const int lrow = tid >> 2, qq = tid & 3;

#pragma unroll
    for (int tile = 0; tile < TILES; tile++) {
        const int rt = (tb + tile) * MT;

#pragma unroll
        for (int it = 0; it < 8; it++) {
            uint32_t h0, l0, h1, l1;
            split_pair(v[it].x, v[it].y, h0, l0);
            split_pair(v[it].z, v[it].w, h1, l1);
            int base = vrow[it] * SW + (vf4[it] << 1);
            *(uint2*)(sm + S_RH + base) = make_uint2(h0, h1);
            *(uint2*)(sm + S_RL + base) = make_uint2(l0, l1);
        }
        if (tile < TILES - 1) {
            const int rtn = (tb + tile + 1) * MT;
#pragma unroll
            for (int it = 0; it < 8; it++)
                v[it] = *(const float4*)(rec + (((rtn + vrow[it]) * E + e) << 6) + (vf4[it] << 2));
        }
        __syncthreads();

        float d[2][4][4];
#pragma unroll
        for (int mt = 0; mt < 2; mt++)
#pragma unroll
            for (int j = 0; j < 4; j++)
#pragma unroll
                for (int c = 0; c < 4; c++) d[mt][j][c] = 0.0f;

#pragma unroll
        for (int ks = 0; ks < 4; ks++) {
            const uint32_t wb = (uint32_t)ks << 5;
            uint32_t AH[2][4], AL[2][4], BH[2][4], BL[2][4];
            ldsm_x4(AH[0], a_h[0] + wb);  ldsm_x4(AH[1], a_h[1] + wb);
            ldsm_x4(AL[0], a_l[0] + wb);  ldsm_x4(AL[1], a_l[1] + wb);
            ldsm_x4(BH[0], b_h[0] + wb);  ldsm_x4(BH[1], b_h[1] + wb);
            ldsm_x4(BL[0], b_l[0] + wb);  ldsm_x4(BL[1], b_l[1] + wb);

#pragma unroll
            for (int mt = 0; mt < 2; mt++)
#pragma unroll
                for (int jp = 0; jp < 2; jp++)
#pragma unroll
                    for (int jj = 0; jj < 2; jj++)
                        mma_bf16(d[mt][(jp << 1) + jj],
                                 AH[mt][0], AH[mt][1], AH[mt][2], AH[mt][3],
                                 BH[jp][jj << 1], BH[jp][(jj << 1) + 1]);
#pragma unroll
            for (int mt = 0; mt < 2; mt++)
#pragma unroll
                for (int jp = 0; jp < 2; jp++)
#pragma unroll
                    for (int jj = 0; jj < 2; jj++)
                        mma_bf16(d[mt][(jp << 1) + jj],
                                 AH[mt][0], AH[mt][1], AH[mt][2], AH[mt][3],
                                 BL[jp][jj << 1], BL[jp][(jj << 1) + 1]);
#pragma unroll
            for (int mt = 0; mt < 2; mt++)
#pragma unroll
                for (int jp = 0; jp < 2; jp++)
#pragma unroll
                    for (int jj = 0; jj < 2; jj++)
                        mma_bf16(d[mt][(jp << 1) + jj],
                                 AL[mt][0], AL[mt][1], AL[mt][2], AL[mt][3],
                                 BH[jp][jj << 1], BH[jp][(jj << 1) + 1]);
        }

#pragma unroll
        for (int mt = 0; mt < 2; mt++)
#pragma unroll
            for (int j = 0; j < 4; j++) {
                const int l0 = nb + (j << 3) + (t << 1);
                const int r0 = mb + (mt << 4) + g;
                sm_h[ l0      * HS + r0    ] = __float2half(d[mt][j][0]);
                sm_h[(l0 + 1) * HS + r0    ] = __float2half(d[mt][j][1]);
                sm_h[ l0      * HS + r0 + 8] = __float2half(d[mt][j][2]);
                sm_h[(l0 + 1) * HS + r0 + 8] = __float2half(d[mt][j][3]);
            }
        __syncthreads();

        {
            __half* dst = ga + ((long)((e << 6) + lrow)) * R + rt;
            const __half* src = sm_h + lrow * HS;
#pragma unroll
            for (int i = 0; i < 4; i++) {
                int off = (((i << 2) + qq) << 3);
                *(uint4*)(dst + off) = *(const uint4*)(src + off);
            }
        }
    }
}

// ---------------------------------------------------------------------------
// Kernel B: windowed RBF, fixed-13 unrolled loop, 2 r/thread, fused finalize.
// grid (L, 8), 256 threads. smem: s_a[E][512] fp32 (dynamic, 64 KB).
// ---------------------------------------------------------------------------
__global__ __launch_bounds__(256)
void rbf_energy(const float* __restrict__ ligc, const float* __restrict__ recc,
                const float* __restrict__ w, const float* __restrict__ b,
                float* __restrict__ out) {
    extern __shared__ float s_a[];            // [E][RTILE2]
    __shared__ float s_lc[P][3];
    __shared__ float s_red[8][P];
    __shared__ int   s_last;

    const int l   = blockIdx.x;
    const int rt  = blockIdx.y * RTILE2;
    const int tid = threadIdx.x;

    if (tid < P * 3) {
        int p = tid / 3, cc = tid % 3;
        s_lc[p][cc] = ligc[p * (L * 3) + l * 3 + cc];
    }
    {
        const __half* ga = reinterpret_cast<const __half*>(g_atn_u);
#pragma unroll
        for (int it = 0; it < 32; it++) {
            int s = tid + (it << 8);
            int e = s >> 8, rr = (s & 255) << 1;
            __half2 v = *(const __half2*)(ga + ((long)(e * L + l)) * R + rt + rr);
            float2 f = __half22float2(v);
            s_a[e * RTILE2 + rr]     = f.x;
            s_a[e * RTILE2 + rr + 1] = f.y;
        }
    }
    __syncthreads();

    float acc[P];
#pragma unroll
    for (int p = 0; p < P; p++) acc[p] = 0.0f;

#pragma unroll
    for (int half = 0; half < 2; half++) {
        const int rr = tid + (half << 8);
        const int r  = rt + rr;
        const float cx = recc[3 * r + 0];
        const float cy = recc[3 * r + 1];
        const float cz = recc[3 * r + 2];

#pragma unroll
        for (int p = 0; p < P; p++) {
            float dx = s_lc[p][0] - cx;
            float dy = s_lc[p][1] - cy;
            float dz = s_lc[p][2] - cz;
            // eps added per-coordinate before sum, as in reference: +3*1e-10
            float d2 = fmaf(dx, dx, fmaf(dy, dy, fmaf(dz, dz, 3.0e-10f)));
            float d;
            asm("sqrt.approx.ftz.f32 %0, %1;" : "=f"(d) : "f"(d2));

            int elo = __float2int_ru((d - WIN) * INV_DELTA);
            elo = max(elo, 0);

            float s = (d - (float)elo * DELTA) * KC;
            float f, u;
            {
                float t0 = -s * s;
                asm("ex2.approx.ftz.f32 %0, %1;" : "=f"(f) : "f"(t0));
                float t1 = fmaf(2.0f * DK, s, -DKSQ);
                asm("ex2.approx.ftz.f32 %0, %1;" : "=f"(u) : "f"(t1));
            }
            float ap = 0.0f;
#pragma unroll
            for (int k = 0; k < NWIN; k++) {
                int e = min(elo + k, E - 1);   // beyond-window terms < 2e-18
                ap = fmaf(s_a[e * RTILE2 + rr], f, ap);
                f *= u;
                u *= C2R;
            }
            acc[p] += ap;
        }
    }

#pragma unroll
    for (int p = 0; p < P; p++) {
        float v = acc[p];
#pragma unroll
        for (int off = 16; off; off >>= 1)
            v += __shfl_down_sync(0xffffffffu, v, off);
        if ((tid & 31) == 0) s_red[tid >> 5][p] = v;
    }
    __syncthreads();
    if (tid < P) {
        float v = 0.0f;
#pragma unroll
        for (int ww = 0; ww < 8; ww++) v += s_red[ww][tid];
        g_part[(l * NRT2 + blockIdx.y) * P + tid] = v;
    }

    // ---- last-block fused finalize (deterministic) ----
    __threadfence();
    if (tid == 0) {
        int n = atomicAdd(&g_done, 1);
        s_last = (n == L * NRT2 - 1);
    }
    __syncthreads();
    if (s_last) {
        const int p    = tid >> 5;
        const int lane = tid & 31;
        float s = 0.0f;
#pragma unroll
        for (int k = 0; k < (L * NRT2) / 32; k++)
            s += g_part[(lane + (k << 5)) * P + p];
#pragma unroll
        for (int off = 16; off; off >>= 1)
            s += __shfl_down_sync(0xffffffffu, s, off);
        if (lane == 0) out[p] = fmaf(s, *w, *b);
        if (tid == 0) g_done = 0;   // reset for next graph replay
    }
}

// ---------------------------------------------------------------------------
extern "C" void kernel_launch(void* const* d_in, const int* in_sizes, int n_in,
                              void* d_out, int out_size) {
    const float* lig_feat   = (const float*)d_in[0];
    const float* rec_feat   = (const float*)d_in[1];
    const float* lig_coords = (const float*)d_in[2];
    const float* rec_coord  = (const float*)d_in[3];
    const float* weight     = (const float*)d_in[4];
    const float* bias       = (const float*)d_in[5];
    float* out = (float*)d_out;

    const int smemA = S_WORDS * (int)sizeof(uint32_t);        // 72704 B
    const int smemB = E * RTILE2 * (int)sizeof(float);        // 65536 B
    cudaFuncSetAttribute(atn_mma,    cudaFuncAttributeMaxDynamicSharedMemorySize, smemA);
    cudaFuncSetAttribute(rbf_energy, cudaFuncAttributeMaxDynamicSharedMemorySize, smemB);

    atn_mma   <<<dim3(E, GRIDY), 256, smemA>>>(lig_feat, rec_feat);
    rbf_energy<<<dim3(L, NRT2), 256, smemB>>>(lig_coords, rec_coord,
                                              weight, bias, out);
}

// round 16
// speedup vs baseline: 1.0824x; 1.0685x over previous
#include <cuda_runtime.h>
#include <cuda_fp16.h>
#include <math.h>
#include <cstdint>

#define L 64
#define R 4096
#define E 32
#define F 64
#define P 8

// ---- GEMM tiling: per block e fixed, 4 rt-tiles of M(r)=128, N(l)=64, K=64 ----
#define MT      128
#define TILES   4
#define GRIDY   (R / (MT * TILES))   // 8
#define SW      36            // smem row stride in b32 words; rows land on banks 4g+t

// epilogue half-buffer row stride (halfwords)
#define HS     136

// ---- RBF tiling ----
#define RTILE2 256
#define NRT2   (R / RTILE2)   // 16
#define EPAD   44             // 32 real rows + 12 zero pad rows (window overrun)

// RBF constants
#define DELTA      (10.0f / 31.0f)
#define INV_DELTA  (31.0f / 10.0f)
#define KC         3.8435917081166394f   // sqrt(log2 e)/|sigma|, sigma = -0.3125
#define DK         1.2398682929408514f   // DELTA * KC
#define DKSQ       1.5372733816041298f   // DK^2
#define C2R        0.1187050163f         // 2^(-2*DK^2)
#define WIN        2.0f
#define NWIN       13                     // fixed window trip count

// scratch: atn[e][l][r] in fp16 (16.75 MB, L2-resident) + per-block partials
__device__ uint4 g_atn_u[E * L * R / 8];
__device__ float g_part[L * NRT2 * P];
__device__ int   g_done = 0;

__device__ __forceinline__ uint32_t s2u(const void* p) {
    uint32_t a;
    asm("{ .reg .u64 t; cvta.to.shared.u64 t, %1; cvt.u32.u64 %0, t; }"
        : "=r"(a) : "l"(p));
    return a;
}

// ---- bf16 helpers -------------------------------------------------------
__device__ __forceinline__ uint32_t pack_bf16(float hi_val, float lo_val) {
    uint32_t r;
    asm("cvt.rn.bf16x2.f32 %0, %1, %2;" : "=r"(r) : "f"(hi_val), "f"(lo_val));
    return r;
}
__device__ __forceinline__ void split_pair(float x, float y,
                                           uint32_t& h, uint32_t& l) {
    h = pack_bf16(y, x);
    float fx = __uint_as_float(h << 16);
    float fy = __uint_as_float(h & 0xffff0000u);
    l = pack_bf16(y - fy, x - fx);
}
__device__ __forceinline__ void mma_bf16(float* d,
                                         uint32_t a0, uint32_t a1,
                                         uint32_t a2, uint32_t a3,
                                         uint32_t b0, uint32_t b1) {
    asm volatile(
        "mma.sync.aligned.m16n8k16.row.col.f32.bf16.bf16.f32 "
        "{%0,%1,%2,%3}, {%4,%5,%6,%7}, {%8,%9}, {%0,%1,%2,%3};"
        : "+f"(d[0]), "+f"(d[1]), "+f"(d[2]), "+f"(d[3])
        : "r"(a0), "r"(a1), "r"(a2), "r"(a3), "r"(b0), "r"(b1));
}
__device__ __forceinline__ void ldsm_x4(uint32_t* r, uint32_t addr) {
    asm volatile("ldmatrix.sync.aligned.m8n8.x4.shared.b16 {%0,%1,%2,%3}, [%4];"
        : "=r"(r[0]), "=r"(r[1]), "=r"(r[2]), "=r"(r[3]) : "r"(addr));
}

// ---------------------------------------------------------------------------
// Kernel A: 3xBF16 mma.sync m16n8k16, 4-tile software pipeline (R14, best A).
// ---------------------------------------------------------------------------
#define S_LH 0
#define S_LL (64 * SW)
#define S_RH (2 * 64 * SW)
#define S_RL (2 * 64 * SW + 128 * SW)
#define S_EPI (2 * 64 * SW + 2 * 128 * SW)
#define S_WORDS (S_EPI + (64 * HS) / 2)

__global__ __launch_bounds__(256)
void atn_mma(const float* __restrict__ lig, const float* __restrict__ rec) {
    extern __shared__ uint32_t sm[];
    const int e   = blockIdx.x;
    const int tb  = blockIdx.y << 2;
    const int tid = threadIdx.x;

#pragma unroll
    for (int it = 0; it < 4; it++) {
        int idx = tid + (it << 8);
        int row = idx >> 4, f4 = idx & 15;
        float4 v = *(const float4*)(lig + ((row * E + e) << 6) + (f4 << 2));
        uint32_t h0, l0, h1, l1;
        split_pair(v.x, v.y, h0, l0);
        split_pair(v.z, v.w, h1, l1);
        int base = row * SW + (f4 << 1);
        *(uint2*)(sm + S_LH + base) = make_uint2(h0, h1);
        *(uint2*)(sm + S_LL + base) = make_uint2(l0, l1);
    }

    int vrow[8], vf4[8];
#pragma unroll
    for (int it = 0; it < 8; it++) {
        int idx = tid + (it << 8);
        vrow[it] = idx >> 4;
        vf4[it]  = idx & 15;
    }

    float4 v[8];
    {
        const int rt0 = tb * MT;
#pragma unroll
        for (int it = 0; it < 8; it++)
            v[it] = *(const float4*)(rec + (((rt0 + vrow[it]) * E + e) << 6) + (vf4[it] << 2));
    }

    const int wid = tid >> 5;
    const int lid = tid & 31;
    const int g   = lid >> 2;
    const int t   = lid & 3;
    const int mb  = (wid & 3) << 5;
    const int nb  = (wid >> 2) << 5;

    const int i8 = lid & 7;
    const int q  = lid >> 3;
    const uint32_t sb = s2u(sm);

    uint32_t a_h[2], a_l[2], b_h[2], b_l[2];
#pragma unroll
    for (int mt = 0; mt < 2; mt++) {
        int row = mb + (mt << 4) + ((q & 1) << 3) + i8;
        uint32_t off = (uint32_t)(row * SW + ((q >> 1) << 2)) << 2;
        a_h[mt] = sb + (S_RH << 2) + off;
        a_l[mt] = sb + (S_RL << 2) + off;
    }
#pragma unroll
    for (int jp = 0; jp < 2; jp++) {
        int row = nb + (jp << 4) + ((q >> 1) << 3) + i8;
        uint32_t off = (uint32_t)(row * SW + ((q & 1) << 2)) << 2;
        b_h[jp] = sb + (S_LH << 2) + off;
        b_l[jp] = sb + (S_LL << 2) + off;
    }

    __half* sm_h = reinterpret_cast<__half*>(sm + S_EPI);
    __half* ga   = reinterpret_cast<__half*>(g_atn_u);
    const int lrow = tid >> 2, qq = tid & 3;

#pragma unroll
    for (int tile = 0; tile < TILES; tile++) {
        const int rt = (tb + tile) * MT;

#pragma unroll
        for (int it = 0; it < 8; it++) {
            uint32_t h0, l0, h1, l1;
            split_pair(v[it].x, v[it].y, h0, l0);
            split_pair(v[it].z, v[it].w, h1, l1);
            int base = vrow[it] * SW + (vf4[it] << 1);
            *(uint2*)(sm + S_RH + base) = make_uint2(h0, h1);
            *(uint2*)(sm + S_RL + base) = make_uint2(l0, l1);
        }
        if (tile < TILES - 1) {
            const int rtn = (tb + tile + 1) * MT;
#pragma unroll
            for (int it = 0; it < 8; it++)
                v[it] = *(const float4*)(rec + (((rtn + vrow[it]) * E + e) << 6) + (vf4[it] << 2));
        }
        __syncthreads();

        float d[2][4][4];
#pragma unroll
        for (int mt = 0; mt < 2; mt++)
#pragma unroll
            for (int j = 0; j < 4; j++)
#pragma unroll
                for (int c = 0; c < 4; c++) d[mt][j][c] = 0.0f;

#pragma unroll
        for (int ks = 0; ks < 4; ks++) {
            const uint32_t wb = (uint32_t)ks << 5;
            uint32_t AH[2][4], AL[2][4], BH[2][4], BL[2][4];
            ldsm_x4(AH[0], a_h[0] + wb);  ldsm_x4(AH[1], a_h[1] + wb);
            ldsm_x4(AL[0], a_l[0] + wb);  ldsm_x4(AL[1], a_l[1] + wb);
            ldsm_x4(BH[0], b_h[0] + wb);  ldsm_x4(BH[1], b_h[1] + wb);
            ldsm_x4(BL[0], b_l[0] + wb);  ldsm_x4(BL[1], b_l[1] + wb);

#pragma unroll
            for (int mt = 0; mt < 2; mt++)
#pragma unroll
                for (int jp = 0; jp < 2; jp++)
#pragma unroll
                    for (int jj = 0; jj < 2; jj++)
                        mma_bf16(d[mt][(jp << 1) + jj],
                                 AH[mt][0], AH[mt][1], AH[mt][2], AH[mt][3],
                                 BH[jp][jj << 1], BH[jp][(jj << 1) + 1]);
#pragma unroll
            for (int mt = 0; mt < 2; mt++)
#pragma unroll
                for (int jp = 0; jp < 2; jp++)
#pragma unroll
                    for (int jj = 0; jj < 2; jj++)
                        mma_bf16(d[mt][(jp << 1) + jj],
                                 AH[mt][0], AH[mt][1], AH[mt][2], AH[mt][3],
                                 BL[jp][jj << 1], BL[jp][(jj << 1) + 1]);
#pragma unroll
            for (int mt = 0; mt < 2; mt++)
#pragma unroll
                for (int jp = 0; jp < 2; jp++)
#pragma unroll
                    for (int jj = 0; jj < 2; jj++)
                        mma_bf16(d[mt][(jp << 1) + jj],
                                 AL[mt][0], AL[mt][1], AL[mt][2], AL[mt][3],
                                 BH[jp][jj << 1], BH[jp][(jj << 1) + 1]);
        }

#pragma unroll
        for (int mt = 0; mt < 2; mt++)
#pragma unroll
            for (int j = 0; j < 4; j++) {
                const int l0 = nb + (j << 3) + (t << 1);
                const int r0 = mb + (mt << 4) + g;
                sm_h[ l0      * HS + r0    ] = __float2half(d[mt][j][0]);
                sm_h[(l0 + 1) * HS + r0    ] = __float2half(d[mt][j][1]);
                sm_h[ l0      * HS + r0 + 8] = __float2half(d[mt][j][2]);
                sm_h[(l0 + 1) * HS + r0 + 8] = __float2half(d[mt][j][3]);
            }
        __syncthreads();

        {
            __half* dst = ga + ((long)((e << 6) + lrow)) * R + rt;
            const __half* src = sm_h + lrow * HS;
#pragma unroll
            for (int i = 0; i < 4; i++) {
                int off = (((i << 2) + qq) << 3);
                *(uint4*)(dst + off) = *(const uint4*)(src + off);
            }
        }
    }
}

// ---------------------------------------------------------------------------
// Kernel B: windowed RBF; zero-padded e-rows -> pure LDS+FMA inner loop.
// grid (L, 16), 256 threads; thread <-> one r. smem s_a[44][256] fp32 (45 KB).
// ---------------------------------------------------------------------------
__global__ __launch_bounds__(256)
void rbf_energy(const float* __restrict__ ligc, const float* __restrict__ recc,
                const float* __restrict__ w, const float* __restrict__ b,
                float* __restrict__ out) {
    extern __shared__ float s_a[];            // [EPAD][RTILE2]
    __shared__ float s_lc[P][3];
    __shared__ float s_red[8][P];
    __shared__ int   s_last;

    const int l   = blockIdx.x;
    const int rt  = blockIdx.y * RTILE2;
    const int tid = threadIdx.x;

    if (tid < P * 3) {
        int p = tid / 3, cc = tid % 3;
        s_lc[p][cc] = ligc[p * (L * 3) + l * 3 + cc];
    }
    // stage real rows 0..31 (half2 vectorized)
    {
        const __half* ga = reinterpret_cast<const __half*>(g_atn_u);
#pragma unroll
        for (int it = 0; it < 16; it++) {
            int idx = tid + (it << 8);
            int e = idx >> 7, c2 = (idx & 127) << 1;
            __half2 v = *(const __half2*)(ga + ((long)(e * L + l)) * R + rt + c2);
            float2 f = __half22float2(v);
            s_a[e * RTILE2 + c2]     = f.x;
            s_a[e * RTILE2 + c2 + 1] = f.y;
        }
        // zero pad rows 32..43
#pragma unroll
        for (int it = 0; it < 12; it++)
            s_a[(E + it) * RTILE2 + tid] = 0.0f;
    }
    __syncthreads();

    const int r = rt + tid;
    const float cx = recc[3 * r + 0];
    const float cy = recc[3 * r + 1];
    const float cz = recc[3 * r + 2];

    float acc[P];
#pragma unroll
    for (int p = 0; p < P; p++) {
        float dx = s_lc[p][0] - cx;
        float dy = s_lc[p][1] - cy;
        float dz = s_lc[p][2] - cz;
        // eps added per-coordinate before sum, as in reference: +3*1e-10
        float d2 = fmaf(dx, dx, fmaf(dy, dy, fmaf(dz, dz, 3.0e-10f)));
        float d;
        asm("sqrt.approx.ftz.f32 %0, %1;" : "=f"(d) : "f"(d2));

        int elo = __float2int_ru((d - WIN) * INV_DELTA);
        elo = max(elo, 0);
        elo = min(elo, E - 1);

        float s = (d - (float)elo * DELTA) * KC;
        float f, u;
        {
            float t0 = -s * s;
            asm("ex2.approx.ftz.f32 %0, %1;" : "=f"(f) : "f"(t0));
            float t1 = fmaf(2.0f * DK, s, -DKSQ);
            asm("ex2.approx.ftz.f32 %0, %1;" : "=f"(u) : "f"(t1));
        }
        const float* pb = s_a + elo * RTILE2 + tid;   // rows elo..elo+12 valid
        float ap = 0.0f;
#pragma unroll
        for (int k = 0; k < NWIN; k++) {              // LDS[imm] + FFMA + 2 FMUL
            ap = fmaf(pb[k * RTILE2], f, ap);
            f *= u;
            u *= C2R;
        }
        acc[p] = ap;
    }

#pragma unroll
    for (int p = 0; p < P; p++) {
        float v = acc[p];
#pragma unroll
        for (int off = 16; off; off >>= 1)
            v += __shfl_down_sync(0xffffffffu, v, off);
        if ((tid & 31) == 0) s_red[tid >> 5][p] = v;
    }
    __syncthreads();
    if (tid < P) {
        float v = 0.0f;
#pragma unroll
        for (int ww = 0; ww < 8; ww++) v += s_red[ww][tid];
        g_part[(l * NRT2 + blockIdx.y) * P + tid] = v;
    }

    // ---- last-block fused finalize (deterministic) ----
    __threadfence();
    if (tid == 0) {
        int n = atomicAdd(&g_done, 1);
        s_last = (n == L * NRT2 - 1);
    }
    __syncthreads();
    if (s_last) {
        const int p    = tid >> 5;
        const int lane = tid & 31;
        float s = 0.0f;
#pragma unroll
        for (int k = 0; k < (L * NRT2) / 32; k++)
            s += g_part[(lane + (k << 5)) * P + p];
#pragma unroll
        for (int off = 16; off; off >>= 1)
            s += __shfl_down_sync(0xffffffffu, s, off);
        if (lane == 0) out[p] = fmaf(s, *w, *b);
        if (tid == 0) g_done = 0;   // reset for next graph replay
    }
}

// ---------------------------------------------------------------------------
extern "C" void kernel_launch(void* const* d_in, const int* in_sizes, int n_in,
                              void* d_out, int out_size) {
    const float* lig_feat   = (const float*)d_in[0];
    const float* rec_feat   = (const float*)d_in[1];
    const float* lig_coords = (const float*)d_in[2];
    const float* rec_coord  = (const float*)d_in[3];
    const float* weight     = (const float*)d_in[4];
    const float* bias       = (const float*)d_in[5];
    float* out = (float*)d_out;

    const int smemA = S_WORDS * (int)sizeof(uint32_t);        // 72704 B
    const int smemB = EPAD * RTILE2 * (int)sizeof(float);     // 45056 B
    cudaFuncSetAttribute(atn_mma,    cudaFuncAttributeMaxDynamicSharedMemorySize, smemA);
    cudaFuncSetAttribute(rbf_energy, cudaFuncAttributeMaxDynamicSharedMemorySize, smemB);

    atn_mma   <<<dim3(E, GRIDY), 256, smemA>>>(lig_feat, rec_feat);
    rbf_energy<<<dim3(L, NRT2), 256, smemB>>>(lig_coords, rec_coord,
                                              weight, bias, out);
}

// round 17
// speedup vs baseline: 1.1100x; 1.0255x over previous
#include <cuda_runtime.h>
#include <cuda_fp16.h>
#include <math.h>
#include <cstdint>

#define L 64
#define R 4096
#define E 32
#define F 64
#define P 8

// ---- GEMM tiling: per block e fixed, 4 rt-tiles of M(r)=128, N(l)=64, K=64 ----
#define MT      128
#define TILES   4
#define GRIDY   (R / (MT * TILES))   // 8
#define SW      36            // smem row stride in b32 words; rows land on banks 4g+t

// epilogue half-buffer row stride (halfwords)
#define HS     136

// ---- RBF tiling ----
#define RTILE2 256
#define NRT2   (R / RTILE2)   // 16
#define EPAD   44             // 32 real rows + 12 zero pad rows (window overrun)

// RBF constants
#define DELTA      (10.0f / 31.0f)
#define INV_DELTA  (31.0f / 10.0f)
#define KC         3.8435917081166394f   // sqrt(log2 e)/|sigma|, sigma = -0.3125
#define DK         1.2398682929408514f   // DELTA * KC
#define DKSQ       1.5372733816041298f   // DK^2
#define C2R        0.1187050163f         // 2^(-2*DK^2)
#define WIN        2.0f
#define NWIN       13                     // fixed window trip count

// scratch: atn[e][l][r] in fp16 (16.75 MB, L2-resident) + per-block partials
__device__ uint4 g_atn_u[E * L * R / 8];
__device__ float g_part[L * NRT2 * P];
__device__ int   g_done = 0;

__device__ __forceinline__ uint32_t s2u(const void* p) {
    uint32_t a;
    asm("{ .reg .u64 t; cvta.to.shared.u64 t, %1; cvt.u32.u64 %0, t; }"
        : "=r"(a) : "l"(p));
    return a;
}

// ---- bf16 helpers -------------------------------------------------------
__device__ __forceinline__ uint32_t pack_bf16(float hi_val, float lo_val) {
    uint32_t r;
    asm("cvt.rn.bf16x2.f32 %0, %1, %2;" : "=r"(r) : "f"(hi_val), "f"(lo_val));
    return r;
}
__device__ __forceinline__ void split_pair(float x, float y,
                                           uint32_t& h, uint32_t& l) {
    h = pack_bf16(y, x);
    float fx = __uint_as_float(h << 16);
    float fy = __uint_as_float(h & 0xffff0000u);
    l = pack_bf16(y - fy, x - fx);
}
__device__ __forceinline__ void mma_bf16(float* d,
                                         uint32_t a0, uint32_t a1,
                                         uint32_t a2, uint32_t a3,
                                         uint32_t b0, uint32_t b1) {
    asm volatile(
        "mma.sync.aligned.m16n8k16.row.col.f32.bf16.bf16.f32 "
        "{%0,%1,%2,%3}, {%4,%5,%6,%7}, {%8,%9}, {%0,%1,%2,%3};"
        : "+f"(d[0]), "+f"(d[1]), "+f"(d[2]), "+f"(d[3])
        : "r"(a0), "r"(a1), "r"(a2), "r"(a3), "r"(b0), "r"(b1));
}
__device__ __forceinline__ void ldsm_x4(uint32_t* r, uint32_t addr) {
    asm volatile("ldmatrix.sync.aligned.m8n8.x4.shared.b16 {%0,%1,%2,%3}, [%4];"
        : "=r"(r[0]), "=r"(r[1]), "=r"(r[2]), "=r"(r[3]) : "r"(addr));
}

// ---------------------------------------------------------------------------
// Kernel A: 3xBF16 mma.sync m16n8k16, 4-tile software pipeline (R14, best A).
// ---------------------------------------------------------------------------
#define S_LH 0
#define S_LL (64 * SW)
#define S_RH (2 * 64 * SW)
#define S_RL (2 * 64 * SW + 128 * SW)
#define S_EPI (2 * 64 * SW + 2 * 128 * SW)
#define S_WORDS (S_EPI + (64 * HS) / 2)

__global__ __launch_bounds__(256)
void atn_mma(const float* __restrict__ lig, const float* __restrict__ rec) {
    extern __shared__ uint32_t sm[];
    const int e   = blockIdx.x;
    const int tb  = blockIdx.y << 2;
    const int tid = threadIdx.x;

#pragma unroll
    for (int it = 0; it < 4; it++) {
        int idx = tid + (it << 8);
        int row = idx >> 4, f4 = idx & 15;
        float4 v = *(const float4*)(lig + ((row * E + e) << 6) + (f4 << 2));
        uint32_t h0, l0, h1, l1;
        split_pair(v.x, v.y, h0, l0);
        split_pair(v.z, v.w, h1, l1);
        int base = row * SW + (f4 << 1);
        *(uint2*)(sm + S_LH + base) = make_uint2(h0, h1);
        *(uint2*)(sm + S_LL + base) = make_uint2(l0, l1);
    }

    int vrow[8], vf4[8];
#pragma unroll
    for (int it = 0; it < 8; it++) {
        int idx = tid + (it << 8);
        vrow[it] = idx >> 4;
        vf4[it]  = idx & 15;
    }

    float4 v[8];
    {
        const int rt0 = tb * MT;
#pragma unroll
        for (int it = 0; it < 8; it++)
            v[it] = *(const float4*)(rec + (((rt0 + vrow[it]) * E + e) << 6) + (vf4[it] << 2));
    }

    const int wid = tid >> 5;
    const int lid = tid & 31;
    const int g   = lid >> 2;
    const int t   = lid & 3;
    const int mb  = (wid & 3) << 5;
    const int nb  = (wid >> 2) << 5;

    const int i8 = lid & 7;
    const int q  = lid >> 3;
    const uint32_t sb = s2u(sm);

    uint32_t a_h[2], a_l[2], b_h[2], b_l[2];
#pragma unroll
    for (int mt = 0; mt < 2; mt++) {
        int row = mb + (mt << 4) + ((q & 1) << 3) + i8;
        uint32_t off = (uint32_t)(row * SW + ((q >> 1) << 2)) << 2;
        a_h[mt] = sb + (S_RH << 2) + off;
        a_l[mt] = sb + (S_RL << 2) + off;
    }
#pragma unroll
    for (int jp = 0; jp < 2; jp++) {
        int row = nb + (jp << 4) + ((q >> 1) << 3) + i8;
        uint32_t off = (uint32_t)(row * SW + ((q & 1) << 2)) << 2;
        b_h[jp] = sb + (S_LH << 2) + off;
        b_l[jp] = sb + (S_LL << 2) + off;
    }

    __half* sm_h = reinterpret_cast<__half*>(sm + S_EPI);
    __half* ga   = reinterpret_cast<__half*>(g_atn_u);
    const int lrow = tid >> 2, qq = tid & 3;

#pragma unroll
    for (int tile = 0; tile < TILES; tile++) {
        const int rt = (tb + tile) * MT;

#pragma unroll
        for (int it = 0; it < 8; it++) {
            uint32_t h0, l0, h1, l1;
            split_pair(v[it].x, v[it].y, h0, l0);
            split_pair(v[it].z, v[it].w, h1, l1);
            int base = vrow[it] * SW + (vf4[it] << 1);
            *(uint2*)(sm + S_RH + base) = make_uint2(h0, h1);
            *(uint2*)(sm + S_RL + base) = make_uint2(l0, l1);
        }
        if (tile < TILES - 1) {
            const int rtn = (tb + tile + 1) * MT;
#pragma unroll
            for (int it = 0; it < 8; it++)
                v[it] = *(const float4*)(rec + (((rtn + vrow[it]) * E + e) << 6) + (vf4[it] << 2));
        }
        __syncthreads();

        float d[2][4][4];
#pragma unroll
        for (int mt = 0; mt < 2; mt++)
#pragma unroll
            for (int j = 0; j < 4; j++)
#pragma unroll
                for (int c = 0; c < 4; c++) d[mt][j][c] = 0.0f;

#pragma unroll
        for (int ks = 0; ks < 4; ks++) {
            const uint32_t wb = (uint32_t)ks << 5;
            uint32_t AH[2][4], AL[2][4], BH[2][4], BL[2][4];
            ldsm_x4(AH[0], a_h[0] + wb);  ldsm_x4(AH[1], a_h[1] + wb);
            ldsm_x4(AL[0], a_l[0] + wb);  ldsm_x4(AL[1], a_l[1] + wb);
            ldsm_x4(BH[0], b_h[0] + wb);  ldsm_x4(BH[1], b_h[1] + wb);
            ldsm_x4(BL[0], b_l[0] + wb);  ldsm_x4(BL[1], b_l[1] + wb);

#pragma unroll
            for (int mt = 0; mt < 2; mt++)
#pragma unroll
                for (int jp = 0; jp < 2; jp++)
#pragma unroll
                    for (int jj = 0; jj < 2; jj++)
                        mma_bf16(d[mt][(jp << 1) + jj],
                                 AH[mt][0], AH[mt][1], AH[mt][2], AH[mt][3],
                                 BH[jp][jj << 1], BH[jp][(jj << 1) + 1]);
#pragma unroll
            for (int mt = 0; mt < 2; mt++)
#pragma unroll
                for (int jp = 0; jp < 2; jp++)
#pragma unroll
                    for (int jj = 0; jj < 2; jj++)
                        mma_bf16(d[mt][(jp << 1) + jj],
                                 AH[mt][0], AH[mt][1], AH[mt][2], AH[mt][3],
                                 BL[jp][jj << 1], BL[jp][(jj << 1) + 1]);
#pragma unroll
            for (int mt = 0; mt < 2; mt++)
#pragma unroll
                for (int jp = 0; jp < 2; jp++)
#pragma unroll
                    for (int jj = 0; jj < 2; jj++)
                        mma_bf16(d[mt][(jp << 1) + jj],
                                 AL[mt][0], AL[mt][1], AL[mt][2], AL[mt][3],
                                 BH[jp][jj << 1], BH[jp][(jj << 1) + 1]);
        }

#pragma unroll
        for (int mt = 0; mt < 2; mt++)
#pragma unroll
            for (int j = 0; j < 4; j++) {
                const int l0 = nb + (j << 3) + (t << 1);
                const int r0 = mb + (mt << 4) + g;
                sm_h[ l0      * HS + r0    ] = __float2half(d[mt][j][0]);
                sm_h[(l0 + 1) * HS + r0    ] = __float2half(d[mt][j][1]);
                sm_h[ l0      * HS + r0 + 8] = __float2half(d[mt][j][2]);
                sm_h[(l0 + 1) * HS + r0 + 8] = __float2half(d[mt][j][3]);
            }
        __syncthreads();

        {
            __half* dst = ga + ((long)((e << 6) + lrow)) * R + rt;
            const __half* src = sm_h + lrow * HS;
#pragma unroll
            for (int i = 0; i < 4; i++) {
                int off = (((i << 2) + qq) << 3);
                *(uint4*)(dst + off) = *(const uint4*)(src + off);
            }
        }
    }
}

// ---------------------------------------------------------------------------
// Kernel B: windowed RBF; zero-padded rows; pose-interleaved (k-outer) loop.
// grid (L, 16), 256 threads; thread <-> one r. smem s_a[44][256] fp32 (45 KB).
// ---------------------------------------------------------------------------
__global__ __launch_bounds__(256)
void rbf_energy(const float* __restrict__ ligc, const float* __restrict__ recc,
                const float* __restrict__ w, const float* __restrict__ b,
                float* __restrict__ out) {
    extern __shared__ float s_a[];            // [EPAD][RTILE2]
    __shared__ float s_lc[P][3];
    __shared__ float s_red[8][P];
    __shared__ int   s_last;

    const int l   = blockIdx.x;
    const int rt  = blockIdx.y * RTILE2;
    const int tid = threadIdx.x;

    if (tid < P * 3) {
        int p = tid / 3, cc = tid % 3;
        s_lc[p][cc] = ligc[p * (L * 3) + l * 3 + cc];
    }
    // stage real rows 0..31 (half2 vectorized)
    {
        const __half* ga = reinterpret_cast<const __half*>(g_atn_u);
#pragma unroll
        for (int it = 0; it < 16; it++) {
            int idx = tid + (it << 8);
            int e = idx >> 7, c2 = (idx & 127) << 1;
            __half2 v = *(const __half2*)(ga + ((long)(e * L + l)) * R + rt + c2);
            float2 f = __half22float2(v);
            s_a[e * RTILE2 + c2]     = f.x;
            s_a[e * RTILE2 + c2 + 1] = f.y;
        }
        // zero pad rows 32..43
#pragma unroll
        for (int it = 0; it < 12; it++)
            s_a[(E + it) * RTILE2 + tid] = 0.0f;
    }
    __syncthreads();

    const int r = rt + tid;
    const float cx = recc[3 * r + 0];
    const float cy = recc[3 * r + 1];
    const float cz = recc[3 * r + 2];

    // ---- per-pose window setup (independent across p) ----
    const float* pb[P];
    float f[P], u[P], ap[P];
#pragma unroll
    for (int p = 0; p < P; p++) {
        float dx = s_lc[p][0] - cx;
        float dy = s_lc[p][1] - cy;
        float dz = s_lc[p][2] - cz;
        // eps added per-coordinate before sum, as in reference: +3*1e-10
        float d2 = fmaf(dx, dx, fmaf(dy, dy, fmaf(dz, dz, 3.0e-10f)));
        float d;
        asm("sqrt.approx.ftz.f32 %0, %1;" : "=f"(d) : "f"(d2));

        int elo = __float2int_ru((d - WIN) * INV_DELTA);
        elo = max(elo, 0);
        elo = min(elo, E - 1);

        float s = (d - (float)elo * DELTA) * KC;
        {
            float t0 = -s * s;
            asm("ex2.approx.ftz.f32 %0, %1;" : "=f"(f[p]) : "f"(t0));
            float t1 = fmaf(2.0f * DK, s, -DKSQ);
            asm("ex2.approx.ftz.f32 %0, %1;" : "=f"(u[p]) : "f"(t1));
        }
        pb[p] = s_a + elo * RTILE2 + tid;     // rows elo..elo+12 valid
        ap[p] = 0.0f;
    }

    // ---- pose-interleaved window: dependency distance 8 on every chain ----
#pragma unroll
    for (int k = 0; k < NWIN; k++)
#pragma unroll
        for (int p = 0; p < P; p++) {
            ap[p] = fmaf(pb[p][k * RTILE2], f[p], ap[p]);
            f[p] *= u[p];
            u[p] *= C2R;
        }

#pragma unroll
    for (int p = 0; p < P; p++) {
        float v = ap[p];
#pragma unroll
        for (int off = 16; off; off >>= 1)
            v += __shfl_down_sync(0xffffffffu, v, off);
        if ((tid & 31) == 0) s_red[tid >> 5][p] = v;
    }
    __syncthreads();
    if (tid < P) {
        float v = 0.0f;
#pragma unroll
        for (int ww = 0; ww < 8; ww++) v += s_red[ww][tid];
        g_part[(l * NRT2 + blockIdx.y) * P + tid] = v;
    }

    // ---- last-block fused finalize (deterministic) ----
    __threadfence();
    if (tid == 0) {
        int n = atomicAdd(&g_done, 1);
        s_last = (n == L * NRT2 - 1);
    }
    __syncthreads();
    if (s_last) {
        const int p    = tid >> 5;
        const int lane = tid & 31;
        float s = 0.0f;
#pragma unroll
        for (int k = 0; k < (L * NRT2) / 32; k++)
            s += g_part[(lane + (k << 5)) * P + p];
#pragma unroll
        for (int off = 16; off; off >>= 1)
            s += __shfl_down_sync(0xffffffffu, s, off);
        if (lane == 0) out[p] = fmaf(s, *w, *b);
        if (tid == 0) g_done = 0;   // reset for next graph replay
    }
}

// ---------------------------------------------------------------------------
extern "C" void kernel_launch(void* const* d_in, const int* in_sizes, int n_in,
                              void* d_out, int out_size) {
    const float* lig_feat   = (const float*)d_in[0];
    const float* rec_feat   = (const float*)d_in[1];
    const float* lig_coords = (const float*)d_in[2];
    const float* rec_coord  = (const float*)d_in[3];
    const float* weight     = (const float*)d_in[4];
    const float* bias       = (const float*)d_in[5];
    float* out = (float*)d_out;

    const int smemA = S_WORDS * (int)sizeof(uint32_t);        // 72704 B
    const int smemB = EPAD * RTILE2 * (int)sizeof(float);     // 45056 B
    cudaFuncSetAttribute(atn_mma,    cudaFuncAttributeMaxDynamicSharedMemorySize, smemA);
    cudaFuncSetAttribute(rbf_energy, cudaFuncAttributeMaxDynamicSharedMemorySize, smemB);

    atn_mma   <<<dim3(E, GRIDY), 256, smemA>>>(lig_feat, rec_feat);
    rbf_energy<<<dim3(L, NRT2), 256, smemB>>>(lig_coords, rec_coord,
                                              weight, bias, out);
}